// round 14
// baseline (speedup 1.0000x reference)
#include <cuda_runtime.h>
#include <cuda_fp16.h>
#include <math.h>

#define B_  8
#define H_  384
#define W_  512
#define HW_ (H_ * W_)
#define NPIX (B_ * HW_)

#define K0 (-1.0f / 12.0f)
#define K1 (2.0f / 3.0f)
#define K3 (-2.0f / 3.0f)
#define K4 (1.0f / 12.0f)

// ---- scratch ----
__device__ __align__(16) __half g_flowhf[B_ * HW_ * 2];    // fp16 interleaved flow f
__device__ __align__(16) __half g_flowhb[B_ * HW_ * 2];    // fp16 interleaved flow b
__device__ __align__(16) __half g_imgp1 [B_ * HW_ * 4];    // img1 packed (r,g,b,0) fp16
__device__ __align__(16) __half g_imgp2 [B_ * HW_ * 4];    // img2 packed
__device__ __align__(16) __half g_diffh[2 * B_ * 3 * HW_]; // per-direction fp16 diff (planar)
__device__ __align__(16) __half g_maskh[2 * NPIX];         // per-direction fp16 mask
__device__ double g_acc[3] = {0.0, 0.0, 0.0};  // energy, entropy, epe (self-resetting)
__device__ unsigned g_done = 0;                // last-block ticket (self-resetting)

__device__ __forceinline__ float sigm(float x) { return 1.0f / (1.0f + __expf(-x)); }

__device__ __forceinline__ void ld4a(const float* __restrict__ p, float* a) {
    float4 v = *reinterpret_cast<const float4*>(p);
    a[0] = v.x; a[1] = v.y; a[2] = v.z; a[3] = v.w;
}
__device__ __forceinline__ float2 ldh2(const __half* __restrict__ p) {
    unsigned u = *reinterpret_cast<const unsigned*>(p);
    return __half22float2(*reinterpret_cast<const __half2*>(&u));
}
__device__ __forceinline__ void ldh4(const __half* __restrict__ p, float* a) {
    uint2 u = *reinterpret_cast<const uint2*>(p);
    float2 f01 = __half22float2(*reinterpret_cast<const __half2*>(&u.x));
    float2 f23 = __half22float2(*reinterpret_cast<const __half2*>(&u.y));
    a[0] = f01.x; a[1] = f01.y; a[2] = f23.x; a[3] = f23.y;
}
__device__ __forceinline__ void ld4h(const __half* __restrict__ p, float* a) {
    uint2 u = *reinterpret_cast<const uint2*>(p);
    float2 f01 = __half22float2(*reinterpret_cast<const __half2*>(&u.x));
    float2 f23 = __half22float2(*reinterpret_cast<const __half2*>(&u.y));
    a[0] = f01.x; a[1] = f01.y; a[2] = f23.x; a[3] = f23.y;
}
__device__ __forceinline__ void ld8h(const __half* __restrict__ p, float* a) {
    uint4 u = *reinterpret_cast<const uint4*>(p);
    float2 f0 = __half22float2(*reinterpret_cast<const __half2*>(&u.x));
    float2 f1 = __half22float2(*reinterpret_cast<const __half2*>(&u.y));
    float2 f2 = __half22float2(*reinterpret_cast<const __half2*>(&u.z));
    float2 f3 = __half22float2(*reinterpret_cast<const __half2*>(&u.w));
    a[0] = f0.x; a[1] = f0.y; a[2] = f1.x; a[3] = f1.y;
    a[4] = f2.x; a[5] = f2.y; a[6] = f3.x; a[7] = f3.y;
}
__device__ __forceinline__ void zero4(float* d) { d[0]=d[1]=d[2]=d[3]=0.0f; }
__device__ __forceinline__ void zero8(float* d) {
    d[0]=d[1]=d[2]=d[3]=d[4]=d[5]=d[6]=d[7]=0.0f;
}

__device__ __forceinline__ void blockReduceAdd(double* dst, float v) {
    __shared__ float ws[32];
    int lane = threadIdx.x & 31;
    int wid  = threadIdx.x >> 5;
#pragma unroll
    for (int o = 16; o; o >>= 1) v += __shfl_down_sync(0xffffffffu, v, o);
    __syncthreads();
    if (lane == 0) ws[wid] = v;
    __syncthreads();
    if (wid == 0) {
        int nw = (blockDim.x + 31) >> 5;
        v = (lane < nw) ? ws[lane] : 0.0f;
#pragma unroll
        for (int o = 16; o; o >>= 1) v += __shfl_down_sync(0xffffffffu, v, o);
        if (lane == 0) atomicAdd(dst, (double)v);
    }
}

// Pass 1: flow samples (fp16 interleaved) + img packing + entropy + EPE. 4 px/thread.
__global__ void sample_kernel(const float* __restrict__ mf, const float* __restrict__ lvf,
                              const float* __restrict__ nf,
                              const float* __restrict__ mb, const float* __restrict__ lvb,
                              const float* __restrict__ nb,
                              const float* __restrict__ tgt,
                              const float* __restrict__ img1,
                              const float* __restrict__ img2) {
    int t = blockIdx.x * blockDim.x + threadIdx.x;
    int b  = t / (HW_ / 4);
    int r4 = t - b * (HW_ / 4);
    int i0 = b * 2 * HW_ + r4 * 4;
    int i1 = i0 + HW_;
    int px = b * HW_ + r4 * 4;

    float m0[4], m1[4], l0[4], l1[4], n0[4], n1[4], t0[4], t1[4];
    ld4a(mf  + i0, m0); ld4a(mf  + i1, m1);
    ld4a(lvf + i0, l0); ld4a(lvf + i1, l1);
    ld4a(nf  + i0, n0); ld4a(nf  + i1, n1);
    ld4a(tgt + i0, t0); ld4a(tgt + i1, t1);

    float ent = 0.0f, epe = 0.0f;
    {
        __half2 fo[4];
#pragma unroll
        for (int i = 0; i < 4; i++) {
            float f0 = m0[i] + __expf(0.5f * l0[i]) * n0[i];
            float f1 = m1[i] + __expf(0.5f * l1[i]) * n1[i];
            fo[i] = __floats2half2_rn(f0, f1);
            ent += l0[i] + l1[i];
            float d0 = m0[i] - t0[i], d1 = m1[i] - t1[i];
            epe += sqrtf(d0 * d0 + d1 * d1);
        }
        *reinterpret_cast<uint4*>(g_flowhf + (size_t)px * 2) =
            *reinterpret_cast<uint4*>(fo);
    }

    ld4a(mb  + i0, m0); ld4a(mb  + i1, m1);
    ld4a(lvb + i0, l0); ld4a(lvb + i1, l1);
    ld4a(nb  + i0, n0); ld4a(nb  + i1, n1);
    {
        __half2 fo[4];
#pragma unroll
        for (int i = 0; i < 4; i++) {
            float f0 = m0[i] + __expf(0.5f * l0[i]) * n0[i];
            float f1 = m1[i] + __expf(0.5f * l1[i]) * n1[i];
            fo[i] = __floats2half2_rn(f0, f1);
            ent += l0[i] + l1[i];
        }
        *reinterpret_cast<uint4*>(g_flowhb + (size_t)px * 2) =
            *reinterpret_cast<uint4*>(fo);
    }

    // ---- pack both images: (r,g,b,0) half4 per pixel ----
    {
        int ii = b * 3 * HW_ + r4 * 4;
        float c0[4], c1[4], c2[4];
        __half2 po[8];

        ld4a(img1 + ii, c0); ld4a(img1 + ii + HW_, c1); ld4a(img1 + ii + 2 * HW_, c2);
#pragma unroll
        for (int i = 0; i < 4; i++) {
            po[2 * i]     = __floats2half2_rn(c0[i], c1[i]);
            po[2 * i + 1] = __floats2half2_rn(c2[i], 0.0f);
        }
        *reinterpret_cast<uint4*>(g_imgp1 + (size_t)px * 4)     = *reinterpret_cast<uint4*>(po);
        *reinterpret_cast<uint4*>(g_imgp1 + (size_t)px * 4 + 8) = *reinterpret_cast<uint4*>(po + 4);

        ld4a(img2 + ii, c0); ld4a(img2 + ii + HW_, c1); ld4a(img2 + ii + 2 * HW_, c2);
#pragma unroll
        for (int i = 0; i < 4; i++) {
            po[2 * i]     = __floats2half2_rn(c0[i], c1[i]);
            po[2 * i + 1] = __floats2half2_rn(c2[i], 0.0f);
        }
        *reinterpret_cast<uint4*>(g_imgp2 + (size_t)px * 4)     = *reinterpret_cast<uint4*>(po);
        *reinterpret_cast<uint4*>(g_imgp2 + (size_t)px * 4 + 8) = *reinterpret_cast<uint4*>(po + 4);
    }

    // data stores done -> allow dependent grid (dir) to launch
    cudaTriggerProgrammaticLaunchCompletion();

    blockReduceAdd(&g_acc[1], ent);
    blockReduceAdd(&g_acc[2], epe);
}

// Pass 2: BOTH directions (blockIdx.y). 1 px/thread on packed fp16 data. PDL consumer.
__global__ void dir_kernel() {
    int dirn = blockIdx.y;
    const __half* __restrict__ fla = dirn ? g_flowhb : g_flowhf;
    const __half* __restrict__ flb = dirn ? g_flowhf : g_flowhb;
    const __half* __restrict__ ipa = dirn ? g_imgp2 : g_imgp1;
    const __half* __restrict__ ipb = dirn ? g_imgp1 : g_imgp2;

    int p = blockIdx.x * blockDim.x + threadIdx.x;
    int b = p / HW_;
    int r = p - b * HW_;
    int y = r / W_;
    int x = r - y * W_;
    const __half* fap = fla + (size_t)(b * HW_) * 2;

    // wait for sample_kernel's writes (prologue above overlapped its tail)
    cudaGridDependencySynchronize();

    float2 fav = ldh2(fap + (size_t)r * 2);
    float fa0 = fav.x, fa1 = fav.y;
    float xq = (float)x + fa0;
    float yq = (float)y + fa1;

    // border mask
    float mx = sigm(xq + 0.5f) * (1.0f - sigm(xq - ((float)W_ - 0.5f)));
    float my = sigm(yq + 0.5f) * (1.0f - sigm(yq - ((float)H_ - 0.5f)));
    float bmask = mx * my;

    // bilinear taps
    float x0f = floorf(xq), y0f = floorf(yq);
    float wx = xq - x0f, wy = yq - y0f;
    int x0 = (int)x0f, y0 = (int)y0f;
    int x1 = x0 + 1,   y1 = y0 + 1;
    float vx0 = (x0 >= 0 && x0 <= W_ - 1) ? 1.0f : 0.0f;
    float vx1 = (x1 >= 0 && x1 <= W_ - 1) ? 1.0f : 0.0f;
    float vy0 = (y0 >= 0 && y0 <= H_ - 1) ? 1.0f : 0.0f;
    float vy1 = (y1 >= 0 && y1 <= H_ - 1) ? 1.0f : 0.0f;
    float w00 = (1.0f - wx) * (1.0f - wy) * vx0 * vy0;
    float w10 = wx * (1.0f - wy) * vx1 * vy0;
    float w01 = (1.0f - wx) * wy * vx0 * vy1;
    float w11 = wx * wy * vx1 * vy1;
    int xc0 = min(max(x0, 0), W_ - 1), xc1 = min(max(x1, 0), W_ - 1);
    int yc0 = min(max(y0, 0), H_ - 1), yc1 = min(max(y1, 0), H_ - 1);
    int o00 = yc0 * W_ + xc0, o10 = yc0 * W_ + xc1;
    int o01 = yc1 * W_ + xc0, o11 = yc1 * W_ + xc1;

    // warp flow_b: 4 x 32-bit gathers (fp16 half2)
    const __half* fbp = flb + (size_t)(b * HW_) * 2;
    float2 g00 = ldh2(fbp + (size_t)o00 * 2);
    float2 g10 = ldh2(fbp + (size_t)o10 * 2);
    float2 g01 = ldh2(fbp + (size_t)o01 * 2);
    float2 g11 = ldh2(fbp + (size_t)o11 * 2);
    float fw0 = w00 * g00.x + w10 * g10.x + w01 * g01.x + w11 * g11.x;
    float fw1 = w00 * g00.y + w10 * g10.y + w01 * g01.y + w11 * g11.y;

    float mag = fa0 * fa0 + fa1 * fa1 + fw0 * fw0 + fw1 * fw1;
    float d0 = fa0 + fw0, d1 = fa1 + fw1;
    float D = d0 * d0 + d1 * d1;
    float occ = 1.0f - sigm(D - (0.01f * mag + 0.5f));
    float m = bmask * occ;
    g_maskh[(size_t)dirn * NPIX + p] = __float2half(m);

    // warp img_b: 4 x 64-bit gathers (packed half4), img_a center: 1 x 64-bit
    const __half* ibp = ipb + (size_t)(b * HW_) * 4;
    const __half* iap = ipa + (size_t)(b * HW_) * 4;
    float t00[4], t10[4], t01[4], t11[4], av[4];
    ldh4(ibp + (size_t)o00 * 4, t00);
    ldh4(ibp + (size_t)o10 * 4, t10);
    ldh4(ibp + (size_t)o01 * 4, t01);
    ldh4(ibp + (size_t)o11 * 4, t11);
    ldh4(iap + (size_t)r * 4, av);

    __half* dw = g_diffh + ((size_t)dirn * B_ + b) * 3 * HW_ + r;
    float A = 0.0f;
#pragma unroll
    for (int c = 0; c < 3; c++) {
        float v = w00 * t00[c] + w10 * t10[c] + w01 * t01[c] + w11 * t11[c];
        float dd = av[c] - v;
        dw[c * HW_] = __float2half(dd);
        A += dd * dd;
    }

    float e = (1.0f - m)
            + sqrtf(A + 1e-5f) * m
            + sqrtf(D + 1e-5f) * m;

    // smoothness (fp16 neighbor loads)
    float s = 0.0f;
    if (x < W_ - 1) {
        float2 nx = ldh2(fap + (size_t)(r + 1) * 2);
        float a0 = nx.x - fa0, a1 = nx.y - fa1;
        s += a0 * a0 + a1 * a1;
    }
    if (y < H_ - 1) {
        float2 nd = ldh2(fap + (size_t)(r + W_) * 2);
        float a0 = nd.x - fa0, a1 = nd.y - fa1;
        s += a0 * a0 + a1 * a1;
    }
    e += sqrtf(s + 1e-5f);

    // diff/mask stores done -> allow grad to launch
    cudaTriggerProgrammaticLaunchCompletion();

    blockReduceAdd(&g_acc[0], e);
}

// Pass 3: BOTH directions (blockIdx.y). 5-tap gradient on fp16 diff. PDL consumer.
// 8 px/thread; last finishing block finalizes the output and resets state.
__global__ void grad_kernel(float* __restrict__ out) {
    int dirn = blockIdx.y;
    int sub = threadIdx.x >> 6;
    int row = blockIdx.x * 4 + sub;
    int b = row / H_;
    int y = row - b * H_;
    int x = (threadIdx.x & 63) * 8;
    int rbase = y * W_ + x;

    const __half* dp = g_diffh + ((size_t)dirn * B_ + b) * 3 * HW_;

    bool hasL  = (x >= 8);
    bool hasR  = (x + 8 < W_);
    bool hasU2 = (y >= 2), hasU1 = (y >= 1);
    bool hasD1 = (y + 1 < H_), hasD2 = (y + 2 < H_);

    // wait for dir_kernel's diff/mask writes
    cudaGridDependencySynchronize();

    float Ct[8];
    zero8(Ct);
#pragma unroll
    for (int c = 0; c < 3; c++) {
        const __half* Dc = dp + c * HW_;
        int o = rbase;
        float arr[12];
        float L4[4], R4[4];
        ld8h(Dc + o, arr + 2);
        if (hasL) ld4h(Dc + o - 4, L4); else zero4(L4);
        if (hasR) ld4h(Dc + o + 8, R4); else zero4(R4);
        arr[0] = L4[2]; arr[1] = L4[3];
        arr[10] = R4[0]; arr[11] = R4[1];

        float u2[8], u1[8], dn1[8], dn2[8];
        if (hasU2) ld8h(Dc + o - 2 * W_, u2);  else zero8(u2);
        if (hasU1) ld8h(Dc + o - W_,     u1);  else zero8(u1);
        if (hasD1) ld8h(Dc + o + W_,     dn1); else zero8(dn1);
        if (hasD2) ld8h(Dc + o + 2 * W_, dn2); else zero8(dn2);

#pragma unroll
        for (int j = 0; j < 8; j++) {
            float gx = K0 * arr[j] + K1 * arr[j + 1] + K3 * arr[j + 3] + K4 * arr[j + 4];
            float gy = K0 * u2[j] + K1 * u1[j] + K3 * dn1[j] + K4 * dn2[j];
            Ct[j] += gx * gx + gy * gy;
        }
    }

    float m[8];
    ld8h(g_maskh + (size_t)dirn * NPIX + (size_t)b * HW_ + rbase, m);
    float e = 0.0f;
#pragma unroll
    for (int j = 0; j < 8; j++) e += sqrtf(Ct[j] + 1e-5f) * m[j];

    blockReduceAdd(&g_acc[0], e);

    // ---- fused finalize ----
    if (threadIdx.x == 0) {
        __threadfence();
        unsigned total = gridDim.x * gridDim.y;
        if (atomicAdd(&g_done, 1u) == total - 1u) {
            double energy  = g_acc[0];
            double entropy = 0.5 * g_acc[1];
            out[0] = (float)((energy - entropy) / (double)B_);
            out[1] = (float)(g_acc[2] / (double)NPIX);
            g_acc[0] = 0.0; g_acc[1] = 0.0; g_acc[2] = 0.0;
            g_done = 0;
        }
    }
}

extern "C" void kernel_launch(void* const* d_in, const int* in_sizes, int n_in,
                              void* d_out, int out_size) {
    const float* meanf   = (const float*)d_in[0];
    const float* logvarf = (const float*)d_in[1];
    const float* meanb   = (const float*)d_in[2];
    const float* logvarb = (const float*)d_in[3];
    const float* img1    = (const float*)d_in[4];
    const float* img2    = (const float*)d_in[5];
    const float* target  = (const float*)d_in[6];
    const float* noisef  = (const float*)d_in[7];
    const float* noiseb  = (const float*)d_in[8];
    float* out = (float*)d_out;

    sample_kernel<<<NPIX / 4 / 256, 256>>>(meanf, logvarf, noisef,
                                           meanb, logvarb, noiseb, target,
                                           img1, img2);

    cudaLaunchAttribute attr[1];
    attr[0].id = cudaLaunchAttributeProgrammaticStreamSerialization;
    attr[0].val.programmaticStreamSerializationAllowed = 1;

    {
        cudaLaunchConfig_t cfg = {};
        cfg.gridDim = dim3(NPIX / 256, 2);
        cfg.blockDim = dim3(256);
        cfg.attrs = attr;
        cfg.numAttrs = 1;
        cudaLaunchKernelEx(&cfg, dir_kernel);
    }
    {
        cudaLaunchConfig_t cfg = {};
        cfg.gridDim = dim3(B_ * H_ / 4, 2);
        cfg.blockDim = dim3(256);
        cfg.attrs = attr;
        cfg.numAttrs = 1;
        cudaLaunchKernelEx(&cfg, grad_kernel, out);
    }
}

// round 15
// speedup vs baseline: 1.0380x; 1.0380x over previous
#include <cuda_runtime.h>
#include <cuda_fp16.h>
#include <math.h>

#define B_  8
#define H_  384
#define W_  512
#define HW_ (H_ * W_)
#define NPIX (B_ * HW_)

#define K0 (-1.0f / 12.0f)
#define K1 (2.0f / 3.0f)
#define K3 (-2.0f / 3.0f)
#define K4 (1.0f / 12.0f)

// ---- scratch ----
__device__ __align__(16) __half g_flowhf[B_ * HW_ * 2];    // fp16 interleaved flow f
__device__ __align__(16) __half g_flowhb[B_ * HW_ * 2];    // fp16 interleaved flow b
__device__ __align__(16) __half g_imgp1 [B_ * HW_ * 4];    // img1 packed (r,g,b,0) fp16
__device__ __align__(16) __half g_imgp2 [B_ * HW_ * 4];    // img2 packed
__device__ __align__(16) __half g_diffh[2 * B_ * 3 * HW_]; // per-direction fp16 diff (planar)
__device__ __align__(16) __half g_maskh[2 * NPIX];         // per-direction fp16 mask
__device__ double g_acc[3] = {0.0, 0.0, 0.0};  // energy, entropy, epe (self-resetting)
__device__ unsigned g_done = 0;                // last-block ticket (self-resetting)

__device__ __forceinline__ float sigm(float x) { return 1.0f / (1.0f + __expf(-x)); }

__device__ __forceinline__ void ld4a(const float* __restrict__ p, float* a) {
    float4 v = *reinterpret_cast<const float4*>(p);
    a[0] = v.x; a[1] = v.y; a[2] = v.z; a[3] = v.w;
}
__device__ __forceinline__ float2 ldh2(const __half* __restrict__ p) {
    unsigned u = *reinterpret_cast<const unsigned*>(p);
    return __half22float2(*reinterpret_cast<const __half2*>(&u));
}
__device__ __forceinline__ void ldh4(const __half* __restrict__ p, float* a) {
    uint2 u = *reinterpret_cast<const uint2*>(p);
    float2 f01 = __half22float2(*reinterpret_cast<const __half2*>(&u.x));
    float2 f23 = __half22float2(*reinterpret_cast<const __half2*>(&u.y));
    a[0] = f01.x; a[1] = f01.y; a[2] = f23.x; a[3] = f23.y;
}
__device__ __forceinline__ void ld4h(const __half* __restrict__ p, float* a) {
    uint2 u = *reinterpret_cast<const uint2*>(p);
    float2 f01 = __half22float2(*reinterpret_cast<const __half2*>(&u.x));
    float2 f23 = __half22float2(*reinterpret_cast<const __half2*>(&u.y));
    a[0] = f01.x; a[1] = f01.y; a[2] = f23.x; a[3] = f23.y;
}
__device__ __forceinline__ void ld8h(const __half* __restrict__ p, float* a) {
    uint4 u = *reinterpret_cast<const uint4*>(p);
    float2 f0 = __half22float2(*reinterpret_cast<const __half2*>(&u.x));
    float2 f1 = __half22float2(*reinterpret_cast<const __half2*>(&u.y));
    float2 f2 = __half22float2(*reinterpret_cast<const __half2*>(&u.z));
    float2 f3 = __half22float2(*reinterpret_cast<const __half2*>(&u.w));
    a[0] = f0.x; a[1] = f0.y; a[2] = f1.x; a[3] = f1.y;
    a[4] = f2.x; a[5] = f2.y; a[6] = f3.x; a[7] = f3.y;
}
__device__ __forceinline__ void zero4(float* d) { d[0]=d[1]=d[2]=d[3]=0.0f; }
__device__ __forceinline__ void zero8(float* d) {
    d[0]=d[1]=d[2]=d[3]=d[4]=d[5]=d[6]=d[7]=0.0f;
}

__device__ __forceinline__ void blockReduceAdd(double* dst, float v) {
    __shared__ float ws[32];
    int lane = threadIdx.x & 31;
    int wid  = threadIdx.x >> 5;
#pragma unroll
    for (int o = 16; o; o >>= 1) v += __shfl_down_sync(0xffffffffu, v, o);
    __syncthreads();
    if (lane == 0) ws[wid] = v;
    __syncthreads();
    if (wid == 0) {
        int nw = (blockDim.x + 31) >> 5;
        v = (lane < nw) ? ws[lane] : 0.0f;
#pragma unroll
        for (int o = 16; o; o >>= 1) v += __shfl_down_sync(0xffffffffu, v, o);
        if (lane == 0) atomicAdd(dst, (double)v);
    }
}

// Pass 1: flow samples (fp16 interleaved) + img packing + entropy + EPE. 4 px/thread.
// grid = (HW/4/256, B)
__global__ void sample_kernel(const float* __restrict__ mf, const float* __restrict__ lvf,
                              const float* __restrict__ nf,
                              const float* __restrict__ mb, const float* __restrict__ lvb,
                              const float* __restrict__ nb,
                              const float* __restrict__ tgt,
                              const float* __restrict__ img1,
                              const float* __restrict__ img2) {
    int b  = blockIdx.y;
    int r4 = blockIdx.x * blockDim.x + threadIdx.x;   // pixel-quad index within image
    int i0 = b * 2 * HW_ + r4 * 4;
    int i1 = i0 + HW_;
    int px = b * HW_ + r4 * 4;

    float m0[4], m1[4], l0[4], l1[4], n0[4], n1[4], t0[4], t1[4];
    ld4a(mf  + i0, m0); ld4a(mf  + i1, m1);
    ld4a(lvf + i0, l0); ld4a(lvf + i1, l1);
    ld4a(nf  + i0, n0); ld4a(nf  + i1, n1);
    ld4a(tgt + i0, t0); ld4a(tgt + i1, t1);

    float ent = 0.0f, epe = 0.0f;
    {
        __half2 fo[4];
#pragma unroll
        for (int i = 0; i < 4; i++) {
            float f0 = m0[i] + __expf(0.5f * l0[i]) * n0[i];
            float f1 = m1[i] + __expf(0.5f * l1[i]) * n1[i];
            fo[i] = __floats2half2_rn(f0, f1);
            ent += l0[i] + l1[i];
            float d0 = m0[i] - t0[i], d1 = m1[i] - t1[i];
            epe += sqrtf(d0 * d0 + d1 * d1);
        }
        *reinterpret_cast<uint4*>(g_flowhf + (size_t)px * 2) =
            *reinterpret_cast<uint4*>(fo);
    }

    ld4a(mb  + i0, m0); ld4a(mb  + i1, m1);
    ld4a(lvb + i0, l0); ld4a(lvb + i1, l1);
    ld4a(nb  + i0, n0); ld4a(nb  + i1, n1);
    {
        __half2 fo[4];
#pragma unroll
        for (int i = 0; i < 4; i++) {
            float f0 = m0[i] + __expf(0.5f * l0[i]) * n0[i];
            float f1 = m1[i] + __expf(0.5f * l1[i]) * n1[i];
            fo[i] = __floats2half2_rn(f0, f1);
            ent += l0[i] + l1[i];
        }
        *reinterpret_cast<uint4*>(g_flowhb + (size_t)px * 2) =
            *reinterpret_cast<uint4*>(fo);
    }

    // ---- pack both images: (r,g,b,0) half4 per pixel ----
    {
        int ii = b * 3 * HW_ + r4 * 4;
        float c0[4], c1[4], c2[4];
        __half2 po[8];

        ld4a(img1 + ii, c0); ld4a(img1 + ii + HW_, c1); ld4a(img1 + ii + 2 * HW_, c2);
#pragma unroll
        for (int i = 0; i < 4; i++) {
            po[2 * i]     = __floats2half2_rn(c0[i], c1[i]);
            po[2 * i + 1] = __floats2half2_rn(c2[i], 0.0f);
        }
        *reinterpret_cast<uint4*>(g_imgp1 + (size_t)px * 4)     = *reinterpret_cast<uint4*>(po);
        *reinterpret_cast<uint4*>(g_imgp1 + (size_t)px * 4 + 8) = *reinterpret_cast<uint4*>(po + 4);

        ld4a(img2 + ii, c0); ld4a(img2 + ii + HW_, c1); ld4a(img2 + ii + 2 * HW_, c2);
#pragma unroll
        for (int i = 0; i < 4; i++) {
            po[2 * i]     = __floats2half2_rn(c0[i], c1[i]);
            po[2 * i + 1] = __floats2half2_rn(c2[i], 0.0f);
        }
        *reinterpret_cast<uint4*>(g_imgp2 + (size_t)px * 4)     = *reinterpret_cast<uint4*>(po);
        *reinterpret_cast<uint4*>(g_imgp2 + (size_t)px * 4 + 8) = *reinterpret_cast<uint4*>(po + 4);
    }

    cudaTriggerProgrammaticLaunchCompletion();

    blockReduceAdd(&g_acc[1], ent);
    blockReduceAdd(&g_acc[2], epe);
}

// Pass 2: grid = (H, B, 2). One row per block; 2 px per thread. PDL consumer.
__global__ void dir_kernel() {
    int dirn = blockIdx.z;
    const __half* __restrict__ fla = dirn ? g_flowhb : g_flowhf;
    const __half* __restrict__ flb = dirn ? g_flowhf : g_flowhb;
    const __half* __restrict__ ipa = dirn ? g_imgp2 : g_imgp1;
    const __half* __restrict__ ipb = dirn ? g_imgp1 : g_imgp2;

    int b = blockIdx.y;
    int y = blockIdx.x;
    int x = threadIdx.x * 2;
    int r = y * W_ + x;

    const __half* fap = fla + (size_t)(b * HW_) * 2;
    const __half* fbp = flb + (size_t)(b * HW_) * 2;
    const __half* iap = ipa + (size_t)(b * HW_) * 4;
    const __half* ibp = ipb + (size_t)(b * HW_) * 4;

    cudaGridDependencySynchronize();

    // center flows for both px (8B), right neighbor of px1, down neighbors (8B)
    float f[4];
    ldh4(fap + (size_t)r * 2, f);
    bool hasR1 = (threadIdx.x < (W_ / 2 - 1));
    float2 fr = make_float2(0.0f, 0.0f);
    if (hasR1) fr = ldh2(fap + (size_t)(r + 2) * 2);
    bool hasD = (y < H_ - 1);
    float fd[4];
    if (hasD) ldh4(fap + (size_t)(r + W_) * 2, fd); else zero4(fd);

    // img_a center, both px (16B)
    float av[8];
    ld8h(iap + (size_t)r * 4, av);

    float e = 0.0f;
    __half mh[2];
    __half2 dh[3];

#pragma unroll
    for (int j = 0; j < 2; j++) {
        float fa0 = f[2 * j], fa1 = f[2 * j + 1];
        float xq = (float)(x + j) + fa0;
        float yq = (float)y + fa1;

        // border mask
        float mx = sigm(xq + 0.5f) * (1.0f - sigm(xq - ((float)W_ - 0.5f)));
        float my = sigm(yq + 0.5f) * (1.0f - sigm(yq - ((float)H_ - 0.5f)));
        float bmask = mx * my;

        // bilinear taps
        float x0f = floorf(xq), y0f = floorf(yq);
        float wx = xq - x0f, wy = yq - y0f;
        int x0 = (int)x0f, y0 = (int)y0f;
        int x1 = x0 + 1,   y1 = y0 + 1;
        float vx0 = (x0 >= 0 && x0 <= W_ - 1) ? 1.0f : 0.0f;
        float vx1 = (x1 >= 0 && x1 <= W_ - 1) ? 1.0f : 0.0f;
        float vy0 = (y0 >= 0 && y0 <= H_ - 1) ? 1.0f : 0.0f;
        float vy1 = (y1 >= 0 && y1 <= H_ - 1) ? 1.0f : 0.0f;
        float w00 = (1.0f - wx) * (1.0f - wy) * vx0 * vy0;
        float w10 = wx * (1.0f - wy) * vx1 * vy0;
        float w01 = (1.0f - wx) * wy * vx0 * vy1;
        float w11 = wx * wy * vx1 * vy1;
        int xc0 = min(max(x0, 0), W_ - 1), xc1 = min(max(x1, 0), W_ - 1);
        int yc0 = min(max(y0, 0), H_ - 1), yc1 = min(max(y1, 0), H_ - 1);
        int o00 = yc0 * W_ + xc0, o10 = yc0 * W_ + xc1;
        int o01 = yc1 * W_ + xc0, o11 = yc1 * W_ + xc1;

        // warp flow_b: 4 x 32-bit gathers
        float2 g00 = ldh2(fbp + (size_t)o00 * 2);
        float2 g10 = ldh2(fbp + (size_t)o10 * 2);
        float2 g01 = ldh2(fbp + (size_t)o01 * 2);
        float2 g11 = ldh2(fbp + (size_t)o11 * 2);
        float fw0 = w00 * g00.x + w10 * g10.x + w01 * g01.x + w11 * g11.x;
        float fw1 = w00 * g00.y + w10 * g10.y + w01 * g01.y + w11 * g11.y;

        float mag = fa0 * fa0 + fa1 * fa1 + fw0 * fw0 + fw1 * fw1;
        float d0 = fa0 + fw0, d1 = fa1 + fw1;
        float D = d0 * d0 + d1 * d1;
        float occ = 1.0f - sigm(D - (0.01f * mag + 0.5f));
        float m = bmask * occ;
        mh[j] = __float2half(m);

        // warp img_b: 4 x 64-bit gathers (packed half4)
        float t00[4], t10[4], t01[4], t11[4];
        ldh4(ibp + (size_t)o00 * 4, t00);
        ldh4(ibp + (size_t)o10 * 4, t10);
        ldh4(ibp + (size_t)o01 * 4, t01);
        ldh4(ibp + (size_t)o11 * 4, t11);

        float A = 0.0f;
#pragma unroll
        for (int c = 0; c < 3; c++) {
            float v = w00 * t00[c] + w10 * t10[c] + w01 * t01[c] + w11 * t11[c];
            float dd = av[4 * j + c] - v;
            if (j == 0) dh[c].x = __float2half(dd);
            else        dh[c].y = __float2half(dd);
            A += dd * dd;
        }

        e += (1.0f - m)
           + sqrtf(A + 1e-5f) * m
           + sqrtf(D + 1e-5f) * m;

        // smoothness
        float s = 0.0f;
        if (j == 0) {
            float a0 = f[2] - fa0, a1 = f[3] - fa1;     // px1 is the x-neighbor
            s += a0 * a0 + a1 * a1;
        } else if (hasR1) {
            float a0 = fr.x - fa0, a1 = fr.y - fa1;
            s += a0 * a0 + a1 * a1;
        }
        if (hasD) {
            float a0 = fd[2 * j] - fa0, a1 = fd[2 * j + 1] - fa1;
            s += a0 * a0 + a1 * a1;
        }
        e += sqrtf(s + 1e-5f);
    }

    // stores: mask (4B) + diff (3 x 4B)
    size_t pp = (size_t)dirn * NPIX + (size_t)b * HW_ + r;
    *reinterpret_cast<__half2*>(g_maskh + pp) = *reinterpret_cast<__half2*>(mh);
    __half* dw = g_diffh + ((size_t)dirn * B_ + b) * 3 * HW_ + r;
#pragma unroll
    for (int c = 0; c < 3; c++)
        *reinterpret_cast<__half2*>(dw + c * HW_) = dh[c];

    cudaTriggerProgrammaticLaunchCompletion();

    blockReduceAdd(&g_acc[0], e);
}

// Pass 3: grid = (H/4, B, 2). 5-tap gradient on fp16 diff, 8 px/thread. PDL consumer.
__global__ void grad_kernel(float* __restrict__ out) {
    int dirn = blockIdx.z;
    int b = blockIdx.y;
    int sub = threadIdx.x >> 6;
    int y = blockIdx.x * 4 + sub;
    int x = (threadIdx.x & 63) * 8;
    int rbase = y * W_ + x;

    const __half* dp = g_diffh + ((size_t)dirn * B_ + b) * 3 * HW_;

    bool hasL  = (x >= 8);
    bool hasR  = (x + 8 < W_);
    bool hasU2 = (y >= 2), hasU1 = (y >= 1);
    bool hasD1 = (y + 1 < H_), hasD2 = (y + 2 < H_);

    cudaGridDependencySynchronize();

    float Ct[8];
    zero8(Ct);
#pragma unroll
    for (int c = 0; c < 3; c++) {
        const __half* Dc = dp + c * HW_;
        int o = rbase;
        float arr[12];
        float L4[4], R4[4];
        ld8h(Dc + o, arr + 2);
        if (hasL) ld4h(Dc + o - 4, L4); else zero4(L4);
        if (hasR) ld4h(Dc + o + 8, R4); else zero4(R4);
        arr[0] = L4[2]; arr[1] = L4[3];
        arr[10] = R4[0]; arr[11] = R4[1];

        float u2[8], u1[8], dn1[8], dn2[8];
        if (hasU2) ld8h(Dc + o - 2 * W_, u2);  else zero8(u2);
        if (hasU1) ld8h(Dc + o - W_,     u1);  else zero8(u1);
        if (hasD1) ld8h(Dc + o + W_,     dn1); else zero8(dn1);
        if (hasD2) ld8h(Dc + o + 2 * W_, dn2); else zero8(dn2);

#pragma unroll
        for (int j = 0; j < 8; j++) {
            float gx = K0 * arr[j] + K1 * arr[j + 1] + K3 * arr[j + 3] + K4 * arr[j + 4];
            float gy = K0 * u2[j] + K1 * u1[j] + K3 * dn1[j] + K4 * dn2[j];
            Ct[j] += gx * gx + gy * gy;
        }
    }

    float m[8];
    ld8h(g_maskh + (size_t)dirn * NPIX + (size_t)b * HW_ + rbase, m);
    float e = 0.0f;
#pragma unroll
    for (int j = 0; j < 8; j++) e += sqrtf(Ct[j] + 1e-5f) * m[j];

    blockReduceAdd(&g_acc[0], e);

    // ---- fused finalize ----
    if (threadIdx.x == 0) {
        __threadfence();
        unsigned total = gridDim.x * gridDim.y * gridDim.z;
        if (atomicAdd(&g_done, 1u) == total - 1u) {
            double energy  = g_acc[0];
            double entropy = 0.5 * g_acc[1];
            out[0] = (float)((energy - entropy) / (double)B_);
            out[1] = (float)(g_acc[2] / (double)NPIX);
            g_acc[0] = 0.0; g_acc[1] = 0.0; g_acc[2] = 0.0;
            g_done = 0;
        }
    }
}

extern "C" void kernel_launch(void* const* d_in, const int* in_sizes, int n_in,
                              void* d_out, int out_size) {
    const float* meanf   = (const float*)d_in[0];
    const float* logvarf = (const float*)d_in[1];
    const float* meanb   = (const float*)d_in[2];
    const float* logvarb = (const float*)d_in[3];
    const float* img1    = (const float*)d_in[4];
    const float* img2    = (const float*)d_in[5];
    const float* target  = (const float*)d_in[6];
    const float* noisef  = (const float*)d_in[7];
    const float* noiseb  = (const float*)d_in[8];
    float* out = (float*)d_out;

    {
        dim3 g(HW_ / 4 / 256, B_);
        sample_kernel<<<g, 256>>>(meanf, logvarf, noisef,
                                  meanb, logvarb, noiseb, target,
                                  img1, img2);
    }

    cudaLaunchAttribute attr[1];
    attr[0].id = cudaLaunchAttributeProgrammaticStreamSerialization;
    attr[0].val.programmaticStreamSerializationAllowed = 1;

    {
        cudaLaunchConfig_t cfg = {};
        cfg.gridDim = dim3(H_, B_, 2);
        cfg.blockDim = dim3(256);
        cfg.attrs = attr;
        cfg.numAttrs = 1;
        cudaLaunchKernelEx(&cfg, dir_kernel);
    }
    {
        cudaLaunchConfig_t cfg = {};
        cfg.gridDim = dim3(H_ / 4, B_, 2);
        cfg.blockDim = dim3(256);
        cfg.attrs = attr;
        cfg.numAttrs = 1;
        cudaLaunchKernelEx(&cfg, grad_kernel, out);
    }
}

// round 16
// speedup vs baseline: 1.1105x; 1.0698x over previous
#include <cuda_runtime.h>
#include <cuda_fp16.h>
#include <math.h>

#define B_  8
#define H_  384
#define W_  512
#define HW_ (H_ * W_)
#define NPIX (B_ * HW_)

#define K0 (-1.0f / 12.0f)
#define K1 (2.0f / 3.0f)
#define K3 (-2.0f / 3.0f)
#define K4 (1.0f / 12.0f)

#define GPAD 8
#define GROWW (W_ + 2 * GPAD)   // 528 halves per smem row

// ---- scratch ----
__device__ __align__(16) __half g_flowhf[B_ * HW_ * 2];    // fp16 interleaved flow f
__device__ __align__(16) __half g_flowhb[B_ * HW_ * 2];    // fp16 interleaved flow b
__device__ __align__(16) __half g_imgp1 [B_ * HW_ * 4];    // img1 packed (r,g,b,0) fp16
__device__ __align__(16) __half g_imgp2 [B_ * HW_ * 4];    // img2 packed
__device__ __align__(16) __half g_diffh[2 * B_ * 3 * HW_]; // per-direction fp16 diff (planar)
__device__ __align__(16) __half g_maskh[2 * NPIX];         // per-direction fp16 mask
__device__ double g_acc[3] = {0.0, 0.0, 0.0};  // energy, entropy, epe (self-resetting)
__device__ unsigned g_done = 0;                // last-block ticket (self-resetting)

__device__ __forceinline__ float sigm(float x) { return 1.0f / (1.0f + __expf(-x)); }

__device__ __forceinline__ void ld4a(const float* __restrict__ p, float* a) {
    float4 v = *reinterpret_cast<const float4*>(p);
    a[0] = v.x; a[1] = v.y; a[2] = v.z; a[3] = v.w;
}
__device__ __forceinline__ float2 ldh2(const __half* p) {
    unsigned u = *reinterpret_cast<const unsigned*>(p);
    return __half22float2(*reinterpret_cast<const __half2*>(&u));
}
__device__ __forceinline__ void ldh4(const __half* p, float* a) {
    uint2 u = *reinterpret_cast<const uint2*>(p);
    float2 f01 = __half22float2(*reinterpret_cast<const __half2*>(&u.x));
    float2 f23 = __half22float2(*reinterpret_cast<const __half2*>(&u.y));
    a[0] = f01.x; a[1] = f01.y; a[2] = f23.x; a[3] = f23.y;
}
__device__ __forceinline__ void ld8h(const __half* p, float* a) {
    uint4 u = *reinterpret_cast<const uint4*>(p);
    float2 f0 = __half22float2(*reinterpret_cast<const __half2*>(&u.x));
    float2 f1 = __half22float2(*reinterpret_cast<const __half2*>(&u.y));
    float2 f2 = __half22float2(*reinterpret_cast<const __half2*>(&u.z));
    float2 f3 = __half22float2(*reinterpret_cast<const __half2*>(&u.w));
    a[0] = f0.x; a[1] = f0.y; a[2] = f1.x; a[3] = f1.y;
    a[4] = f2.x; a[5] = f2.y; a[6] = f3.x; a[7] = f3.y;
}
__device__ __forceinline__ void zero4(float* d) { d[0]=d[1]=d[2]=d[3]=0.0f; }
__device__ __forceinline__ void zero8(float* d) {
    d[0]=d[1]=d[2]=d[3]=d[4]=d[5]=d[6]=d[7]=0.0f;
}

__device__ __forceinline__ void blockReduceAdd(double* dst, float v) {
    __shared__ float ws[32];
    int lane = threadIdx.x & 31;
    int wid  = threadIdx.x >> 5;
#pragma unroll
    for (int o = 16; o; o >>= 1) v += __shfl_down_sync(0xffffffffu, v, o);
    __syncthreads();
    if (lane == 0) ws[wid] = v;
    __syncthreads();
    if (wid == 0) {
        int nw = (blockDim.x + 31) >> 5;
        v = (lane < nw) ? ws[lane] : 0.0f;
#pragma unroll
        for (int o = 16; o; o >>= 1) v += __shfl_down_sync(0xffffffffu, v, o);
        if (lane == 0) atomicAdd(dst, (double)v);
    }
}

// Pass 1: flow samples (fp16 interleaved) + img packing + entropy + EPE. 4 px/thread.
// grid = (HW/4/256, B)
__global__ void sample_kernel(const float* __restrict__ mf, const float* __restrict__ lvf,
                              const float* __restrict__ nf,
                              const float* __restrict__ mb, const float* __restrict__ lvb,
                              const float* __restrict__ nb,
                              const float* __restrict__ tgt,
                              const float* __restrict__ img1,
                              const float* __restrict__ img2) {
    int b  = blockIdx.y;
    int r4 = blockIdx.x * blockDim.x + threadIdx.x;
    int i0 = b * 2 * HW_ + r4 * 4;
    int i1 = i0 + HW_;
    int px = b * HW_ + r4 * 4;

    float m0[4], m1[4], l0[4], l1[4], n0[4], n1[4], t0[4], t1[4];
    ld4a(mf  + i0, m0); ld4a(mf  + i1, m1);
    ld4a(lvf + i0, l0); ld4a(lvf + i1, l1);
    ld4a(nf  + i0, n0); ld4a(nf  + i1, n1);
    ld4a(tgt + i0, t0); ld4a(tgt + i1, t1);

    float ent = 0.0f, epe = 0.0f;
    {
        __half2 fo[4];
#pragma unroll
        for (int i = 0; i < 4; i++) {
            float f0 = m0[i] + __expf(0.5f * l0[i]) * n0[i];
            float f1 = m1[i] + __expf(0.5f * l1[i]) * n1[i];
            fo[i] = __floats2half2_rn(f0, f1);
            ent += l0[i] + l1[i];
            float d0 = m0[i] - t0[i], d1 = m1[i] - t1[i];
            epe += sqrtf(d0 * d0 + d1 * d1);
        }
        *reinterpret_cast<uint4*>(g_flowhf + (size_t)px * 2) =
            *reinterpret_cast<uint4*>(fo);
    }

    ld4a(mb  + i0, m0); ld4a(mb  + i1, m1);
    ld4a(lvb + i0, l0); ld4a(lvb + i1, l1);
    ld4a(nb  + i0, n0); ld4a(nb  + i1, n1);
    {
        __half2 fo[4];
#pragma unroll
        for (int i = 0; i < 4; i++) {
            float f0 = m0[i] + __expf(0.5f * l0[i]) * n0[i];
            float f1 = m1[i] + __expf(0.5f * l1[i]) * n1[i];
            fo[i] = __floats2half2_rn(f0, f1);
            ent += l0[i] + l1[i];
        }
        *reinterpret_cast<uint4*>(g_flowhb + (size_t)px * 2) =
            *reinterpret_cast<uint4*>(fo);
    }

    // ---- pack both images: (r,g,b,0) half4 per pixel ----
    {
        int ii = b * 3 * HW_ + r4 * 4;
        float c0[4], c1[4], c2[4];
        __half2 po[8];

        ld4a(img1 + ii, c0); ld4a(img1 + ii + HW_, c1); ld4a(img1 + ii + 2 * HW_, c2);
#pragma unroll
        for (int i = 0; i < 4; i++) {
            po[2 * i]     = __floats2half2_rn(c0[i], c1[i]);
            po[2 * i + 1] = __floats2half2_rn(c2[i], 0.0f);
        }
        *reinterpret_cast<uint4*>(g_imgp1 + (size_t)px * 4)     = *reinterpret_cast<uint4*>(po);
        *reinterpret_cast<uint4*>(g_imgp1 + (size_t)px * 4 + 8) = *reinterpret_cast<uint4*>(po + 4);

        ld4a(img2 + ii, c0); ld4a(img2 + ii + HW_, c1); ld4a(img2 + ii + 2 * HW_, c2);
#pragma unroll
        for (int i = 0; i < 4; i++) {
            po[2 * i]     = __floats2half2_rn(c0[i], c1[i]);
            po[2 * i + 1] = __floats2half2_rn(c2[i], 0.0f);
        }
        *reinterpret_cast<uint4*>(g_imgp2 + (size_t)px * 4)     = *reinterpret_cast<uint4*>(po);
        *reinterpret_cast<uint4*>(g_imgp2 + (size_t)px * 4 + 8) = *reinterpret_cast<uint4*>(po + 4);
    }

    cudaTriggerProgrammaticLaunchCompletion();

    blockReduceAdd(&g_acc[1], ent);
    blockReduceAdd(&g_acc[2], epe);
}

// Pass 2: grid = (H, B, 2). One row per block; 2 px per thread. PDL consumer.
__global__ void dir_kernel() {
    int dirn = blockIdx.z;
    const __half* __restrict__ fla = dirn ? g_flowhb : g_flowhf;
    const __half* __restrict__ flb = dirn ? g_flowhf : g_flowhb;
    const __half* __restrict__ ipa = dirn ? g_imgp2 : g_imgp1;
    const __half* __restrict__ ipb = dirn ? g_imgp1 : g_imgp2;

    int b = blockIdx.y;
    int y = blockIdx.x;
    int x = threadIdx.x * 2;
    int r = y * W_ + x;

    const __half* fap = fla + (size_t)(b * HW_) * 2;
    const __half* fbp = flb + (size_t)(b * HW_) * 2;
    const __half* iap = ipa + (size_t)(b * HW_) * 4;
    const __half* ibp = ipb + (size_t)(b * HW_) * 4;

    cudaGridDependencySynchronize();

    float f[4];
    ldh4(fap + (size_t)r * 2, f);
    bool hasR1 = (threadIdx.x < (W_ / 2 - 1));
    float2 fr = make_float2(0.0f, 0.0f);
    if (hasR1) fr = ldh2(fap + (size_t)(r + 2) * 2);
    bool hasD = (y < H_ - 1);
    float fd[4];
    if (hasD) ldh4(fap + (size_t)(r + W_) * 2, fd); else zero4(fd);

    float av[8];
    ld8h(iap + (size_t)r * 4, av);

    float e = 0.0f;
    __half mh[2];
    __half2 dh[3];

#pragma unroll
    for (int j = 0; j < 2; j++) {
        float fa0 = f[2 * j], fa1 = f[2 * j + 1];
        float xq = (float)(x + j) + fa0;
        float yq = (float)y + fa1;

        float mx = sigm(xq + 0.5f) * (1.0f - sigm(xq - ((float)W_ - 0.5f)));
        float my = sigm(yq + 0.5f) * (1.0f - sigm(yq - ((float)H_ - 0.5f)));
        float bmask = mx * my;

        float x0f = floorf(xq), y0f = floorf(yq);
        float wx = xq - x0f, wy = yq - y0f;
        int x0 = (int)x0f, y0 = (int)y0f;
        int x1 = x0 + 1,   y1 = y0 + 1;
        float vx0 = (x0 >= 0 && x0 <= W_ - 1) ? 1.0f : 0.0f;
        float vx1 = (x1 >= 0 && x1 <= W_ - 1) ? 1.0f : 0.0f;
        float vy0 = (y0 >= 0 && y0 <= H_ - 1) ? 1.0f : 0.0f;
        float vy1 = (y1 >= 0 && y1 <= H_ - 1) ? 1.0f : 0.0f;
        float w00 = (1.0f - wx) * (1.0f - wy) * vx0 * vy0;
        float w10 = wx * (1.0f - wy) * vx1 * vy0;
        float w01 = (1.0f - wx) * wy * vx0 * vy1;
        float w11 = wx * wy * vx1 * vy1;
        int xc0 = min(max(x0, 0), W_ - 1), xc1 = min(max(x1, 0), W_ - 1);
        int yc0 = min(max(y0, 0), H_ - 1), yc1 = min(max(y1, 0), H_ - 1);
        int o00 = yc0 * W_ + xc0, o10 = yc0 * W_ + xc1;
        int o01 = yc1 * W_ + xc0, o11 = yc1 * W_ + xc1;

        float2 g00 = ldh2(fbp + (size_t)o00 * 2);
        float2 g10 = ldh2(fbp + (size_t)o10 * 2);
        float2 g01 = ldh2(fbp + (size_t)o01 * 2);
        float2 g11 = ldh2(fbp + (size_t)o11 * 2);
        float fw0 = w00 * g00.x + w10 * g10.x + w01 * g01.x + w11 * g11.x;
        float fw1 = w00 * g00.y + w10 * g10.y + w01 * g01.y + w11 * g11.y;

        float mag = fa0 * fa0 + fa1 * fa1 + fw0 * fw0 + fw1 * fw1;
        float d0 = fa0 + fw0, d1 = fa1 + fw1;
        float D = d0 * d0 + d1 * d1;
        float occ = 1.0f - sigm(D - (0.01f * mag + 0.5f));
        float m = bmask * occ;
        mh[j] = __float2half(m);

        float t00[4], t10[4], t01[4], t11[4];
        ldh4(ibp + (size_t)o00 * 4, t00);
        ldh4(ibp + (size_t)o10 * 4, t10);
        ldh4(ibp + (size_t)o01 * 4, t01);
        ldh4(ibp + (size_t)o11 * 4, t11);

        float A = 0.0f;
#pragma unroll
        for (int c = 0; c < 3; c++) {
            float v = w00 * t00[c] + w10 * t10[c] + w01 * t01[c] + w11 * t11[c];
            float dd = av[4 * j + c] - v;
            if (j == 0) dh[c].x = __float2half(dd);
            else        dh[c].y = __float2half(dd);
            A += dd * dd;
        }

        e += (1.0f - m)
           + sqrtf(A + 1e-5f) * m
           + sqrtf(D + 1e-5f) * m;

        float s = 0.0f;
        if (j == 0) {
            float a0 = f[2] - fa0, a1 = f[3] - fa1;
            s += a0 * a0 + a1 * a1;
        } else if (hasR1) {
            float a0 = fr.x - fa0, a1 = fr.y - fa1;
            s += a0 * a0 + a1 * a1;
        }
        if (hasD) {
            float a0 = fd[2 * j] - fa0, a1 = fd[2 * j + 1] - fa1;
            s += a0 * a0 + a1 * a1;
        }
        e += sqrtf(s + 1e-5f);
    }

    size_t pp = (size_t)dirn * NPIX + (size_t)b * HW_ + r;
    *reinterpret_cast<__half2*>(g_maskh + pp) = *reinterpret_cast<__half2*>(mh);
    __half* dw = g_diffh + ((size_t)dirn * B_ + b) * 3 * HW_ + r;
#pragma unroll
    for (int c = 0; c < 3; c++)
        *reinterpret_cast<__half2*>(dw + c * HW_) = dh[c];

    cudaTriggerProgrammaticLaunchCompletion();

    blockReduceAdd(&g_acc[0], e);
}

// Pass 3: grid = (H/4, B, 2). 5-tap gradient on fp16 diff via smem tile.
// Block stages 8 rows x 512 x 3ch of diff into smem, stencil runs from smem.
__global__ void __launch_bounds__(256) grad_kernel(float* __restrict__ out) {
    __shared__ __half sd[3][8][GROWW];   // 25,344 B

    int dirn = blockIdx.z;
    int b = blockIdx.y;
    int y0 = blockIdx.x * 4;
    int tid = threadIdx.x;

    const __half* dp = g_diffh + ((size_t)dirn * B_ + b) * 3 * HW_;

    // zero the left/right aprons: 3ch x 8rows x 2 sides, 8 halves (16B) each
    if (tid < 48) {
        int c = tid / 16;
        int k = (tid & 15) >> 1;
        int side = tid & 1;
        uint4 z = make_uint4(0, 0, 0, 0);
        *reinterpret_cast<uint4*>(&sd[c][k][side ? (GPAD + W_) : 0]) = z;
    }

    cudaGridDependencySynchronize();

    // cooperative load: 3ch x 8 rows x 64 chunks of 8 halves = 1536 chunks
#pragma unroll
    for (int i = 0; i < 6; i++) {
        int id = tid + i * 256;
        int c   = id >> 9;         // /512
        int rem = id & 511;
        int k   = rem >> 6;
        int xc  = rem & 63;
        int yy  = y0 - 2 + k;
        uint4 v = make_uint4(0, 0, 0, 0);
        if (yy >= 0 && yy < H_)
            v = *reinterpret_cast<const uint4*>(dp + c * HW_ + yy * W_ + xc * 8);
        *reinterpret_cast<uint4*>(&sd[c][k][GPAD + xc * 8]) = v;
    }
    __syncthreads();

    int sub = tid >> 6;                 // 0..3: output row within tile
    int x = (tid & 63) * 8;
    int kc = sub + 2;                   // center row in smem
    int y = y0 + sub;

    float Ct[8];
    zero8(Ct);
#pragma unroll
    for (int c = 0; c < 3; c++) {
        float arr[12];
        ld8h(&sd[c][kc][GPAD + x], arr + 2);
        float2 lf = ldh2(&sd[c][kc][GPAD + x - 2]);
        float2 rf = ldh2(&sd[c][kc][GPAD + x + 8]);
        arr[0] = lf.x; arr[1] = lf.y;
        arr[10] = rf.x; arr[11] = rf.y;

        float u2[8], u1[8], dn1[8], dn2[8];
        ld8h(&sd[c][kc - 2][GPAD + x], u2);
        ld8h(&sd[c][kc - 1][GPAD + x], u1);
        ld8h(&sd[c][kc + 1][GPAD + x], dn1);
        ld8h(&sd[c][kc + 2][GPAD + x], dn2);

#pragma unroll
        for (int j = 0; j < 8; j++) {
            float gx = K0 * arr[j] + K1 * arr[j + 1] + K3 * arr[j + 3] + K4 * arr[j + 4];
            float gy = K0 * u2[j] + K1 * u1[j] + K3 * dn1[j] + K4 * dn2[j];
            Ct[j] += gx * gx + gy * gy;
        }
    }

    float m[8];
    ld8h(g_maskh + (size_t)dirn * NPIX + (size_t)b * HW_ + (size_t)y * W_ + x, m);
    float e = 0.0f;
#pragma unroll
    for (int j = 0; j < 8; j++) e += sqrtf(Ct[j] + 1e-5f) * m[j];

    blockReduceAdd(&g_acc[0], e);

    // ---- fused finalize ----
    if (threadIdx.x == 0) {
        __threadfence();
        unsigned total = gridDim.x * gridDim.y * gridDim.z;
        if (atomicAdd(&g_done, 1u) == total - 1u) {
            double energy  = g_acc[0];
            double entropy = 0.5 * g_acc[1];
            out[0] = (float)((energy - entropy) / (double)B_);
            out[1] = (float)(g_acc[2] / (double)NPIX);
            g_acc[0] = 0.0; g_acc[1] = 0.0; g_acc[2] = 0.0;
            g_done = 0;
        }
    }
}

extern "C" void kernel_launch(void* const* d_in, const int* in_sizes, int n_in,
                              void* d_out, int out_size) {
    const float* meanf   = (const float*)d_in[0];
    const float* logvarf = (const float*)d_in[1];
    const float* meanb   = (const float*)d_in[2];
    const float* logvarb = (const float*)d_in[3];
    const float* img1    = (const float*)d_in[4];
    const float* img2    = (const float*)d_in[5];
    const float* target  = (const float*)d_in[6];
    const float* noisef  = (const float*)d_in[7];
    const float* noiseb  = (const float*)d_in[8];
    float* out = (float*)d_out;

    {
        dim3 g(HW_ / 4 / 256, B_);
        sample_kernel<<<g, 256>>>(meanf, logvarf, noisef,
                                  meanb, logvarb, noiseb, target,
                                  img1, img2);
    }

    cudaLaunchAttribute attr[1];
    attr[0].id = cudaLaunchAttributeProgrammaticStreamSerialization;
    attr[0].val.programmaticStreamSerializationAllowed = 1;

    {
        cudaLaunchConfig_t cfg = {};
        cfg.gridDim = dim3(H_, B_, 2);
        cfg.blockDim = dim3(256);
        cfg.attrs = attr;
        cfg.numAttrs = 1;
        cudaLaunchKernelEx(&cfg, dir_kernel);
    }
    {
        cudaLaunchConfig_t cfg = {};
        cfg.gridDim = dim3(H_ / 4, B_, 2);
        cfg.blockDim = dim3(256);
        cfg.attrs = attr;
        cfg.numAttrs = 1;
        cudaLaunchKernelEx(&cfg, grad_kernel, out);
    }
}

// round 17
// speedup vs baseline: 1.2089x; 1.0886x over previous
#include <cuda_runtime.h>
#include <cuda_fp16.h>
#include <math.h>

#define B_  8
#define H_  384
#define W_  512
#define HW_ (H_ * W_)
#define NPIX (B_ * HW_)

#define K0 (-1.0f / 12.0f)
#define K1 (2.0f / 3.0f)
#define K3 (-2.0f / 3.0f)
#define K4 (1.0f / 12.0f)

#define GPAD 8
#define GROWW (W_ + 2 * GPAD)   // 528 halves per smem row

// ---- scratch ----
__device__ __align__(16) __half g_flowhf[B_ * HW_ * 2];    // fp16 interleaved flow f
__device__ __align__(16) __half g_flowhb[B_ * HW_ * 2];    // fp16 interleaved flow b
__device__ __align__(16) __half g_imgp1 [B_ * HW_ * 4];    // img1 packed (r,g,b,0) fp16
__device__ __align__(16) __half g_imgp2 [B_ * HW_ * 4];    // img2 packed
__device__ __align__(16) __half g_diffh[2 * B_ * 3 * HW_]; // per-direction fp16 diff (planar)
__device__ __align__(16) __half g_maskh[2 * NPIX];         // per-direction fp16 mask
__device__ double g_acc[3] = {0.0, 0.0, 0.0};  // energy, entropy, epe (self-resetting)
__device__ unsigned g_done = 0;                // last-block ticket (self-resetting)

// fast sigmoid: MUFU.EX2 + MUFU.RCP
__device__ __forceinline__ float sigm(float x) {
    return __fdividef(1.0f, 1.0f + __expf(-x));
}
// fast sqrt for strictly-positive x (x >= 1e-5 at all call sites)
__device__ __forceinline__ float fsqrtp(float x) { return x * rsqrtf(x); }
// fast sqrt safe at 0
__device__ __forceinline__ float fsqrt0(float x) {
    return x * rsqrtf(fmaxf(x, 1e-30f));
}

__device__ __forceinline__ void ld4a(const float* __restrict__ p, float* a) {
    float4 v = *reinterpret_cast<const float4*>(p);
    a[0] = v.x; a[1] = v.y; a[2] = v.z; a[3] = v.w;
}
__device__ __forceinline__ float2 ldh2(const __half* p) {
    unsigned u = *reinterpret_cast<const unsigned*>(p);
    return __half22float2(*reinterpret_cast<const __half2*>(&u));
}
__device__ __forceinline__ void ldh4(const __half* p, float* a) {
    uint2 u = *reinterpret_cast<const uint2*>(p);
    float2 f01 = __half22float2(*reinterpret_cast<const __half2*>(&u.x));
    float2 f23 = __half22float2(*reinterpret_cast<const __half2*>(&u.y));
    a[0] = f01.x; a[1] = f01.y; a[2] = f23.x; a[3] = f23.y;
}
__device__ __forceinline__ void ld8h(const __half* p, float* a) {
    uint4 u = *reinterpret_cast<const uint4*>(p);
    float2 f0 = __half22float2(*reinterpret_cast<const __half2*>(&u.x));
    float2 f1 = __half22float2(*reinterpret_cast<const __half2*>(&u.y));
    float2 f2 = __half22float2(*reinterpret_cast<const __half2*>(&u.z));
    float2 f3 = __half22float2(*reinterpret_cast<const __half2*>(&u.w));
    a[0] = f0.x; a[1] = f0.y; a[2] = f1.x; a[3] = f1.y;
    a[4] = f2.x; a[5] = f2.y; a[6] = f3.x; a[7] = f3.y;
}
__device__ __forceinline__ void zero4(float* d) { d[0]=d[1]=d[2]=d[3]=0.0f; }
__device__ __forceinline__ void zero8(float* d) {
    d[0]=d[1]=d[2]=d[3]=d[4]=d[5]=d[6]=d[7]=0.0f;
}

__device__ __forceinline__ void blockReduceAdd(double* dst, float v) {
    __shared__ float ws[32];
    int lane = threadIdx.x & 31;
    int wid  = threadIdx.x >> 5;
#pragma unroll
    for (int o = 16; o; o >>= 1) v += __shfl_down_sync(0xffffffffu, v, o);
    __syncthreads();
    if (lane == 0) ws[wid] = v;
    __syncthreads();
    if (wid == 0) {
        int nw = (blockDim.x + 31) >> 5;
        v = (lane < nw) ? ws[lane] : 0.0f;
#pragma unroll
        for (int o = 16; o; o >>= 1) v += __shfl_down_sync(0xffffffffu, v, o);
        if (lane == 0) atomicAdd(dst, (double)v);
    }
}

// Pass 1: flow samples (fp16 interleaved) + img packing + entropy + EPE. 4 px/thread.
// grid = (HW/4/256, B)
__global__ void sample_kernel(const float* __restrict__ mf, const float* __restrict__ lvf,
                              const float* __restrict__ nf,
                              const float* __restrict__ mb, const float* __restrict__ lvb,
                              const float* __restrict__ nb,
                              const float* __restrict__ tgt,
                              const float* __restrict__ img1,
                              const float* __restrict__ img2) {
    int b  = blockIdx.y;
    int r4 = blockIdx.x * blockDim.x + threadIdx.x;
    int i0 = b * 2 * HW_ + r4 * 4;
    int i1 = i0 + HW_;
    int px = b * HW_ + r4 * 4;

    float m0[4], m1[4], l0[4], l1[4], n0[4], n1[4], t0[4], t1[4];
    ld4a(mf  + i0, m0); ld4a(mf  + i1, m1);
    ld4a(lvf + i0, l0); ld4a(lvf + i1, l1);
    ld4a(nf  + i0, n0); ld4a(nf  + i1, n1);
    ld4a(tgt + i0, t0); ld4a(tgt + i1, t1);

    float ent = 0.0f, epe = 0.0f;
    {
        __half2 fo[4];
#pragma unroll
        for (int i = 0; i < 4; i++) {
            float f0 = m0[i] + __expf(0.5f * l0[i]) * n0[i];
            float f1 = m1[i] + __expf(0.5f * l1[i]) * n1[i];
            fo[i] = __floats2half2_rn(f0, f1);
            ent += l0[i] + l1[i];
            float d0 = m0[i] - t0[i], d1 = m1[i] - t1[i];
            epe += fsqrt0(d0 * d0 + d1 * d1);
        }
        *reinterpret_cast<uint4*>(g_flowhf + (size_t)px * 2) =
            *reinterpret_cast<uint4*>(fo);
    }

    ld4a(mb  + i0, m0); ld4a(mb  + i1, m1);
    ld4a(lvb + i0, l0); ld4a(lvb + i1, l1);
    ld4a(nb  + i0, n0); ld4a(nb  + i1, n1);
    {
        __half2 fo[4];
#pragma unroll
        for (int i = 0; i < 4; i++) {
            float f0 = m0[i] + __expf(0.5f * l0[i]) * n0[i];
            float f1 = m1[i] + __expf(0.5f * l1[i]) * n1[i];
            fo[i] = __floats2half2_rn(f0, f1);
            ent += l0[i] + l1[i];
        }
        *reinterpret_cast<uint4*>(g_flowhb + (size_t)px * 2) =
            *reinterpret_cast<uint4*>(fo);
    }

    // ---- pack both images: (r,g,b,0) half4 per pixel ----
    {
        int ii = b * 3 * HW_ + r4 * 4;
        float c0[4], c1[4], c2[4];
        __half2 po[8];

        ld4a(img1 + ii, c0); ld4a(img1 + ii + HW_, c1); ld4a(img1 + ii + 2 * HW_, c2);
#pragma unroll
        for (int i = 0; i < 4; i++) {
            po[2 * i]     = __floats2half2_rn(c0[i], c1[i]);
            po[2 * i + 1] = __floats2half2_rn(c2[i], 0.0f);
        }
        *reinterpret_cast<uint4*>(g_imgp1 + (size_t)px * 4)     = *reinterpret_cast<uint4*>(po);
        *reinterpret_cast<uint4*>(g_imgp1 + (size_t)px * 4 + 8) = *reinterpret_cast<uint4*>(po + 4);

        ld4a(img2 + ii, c0); ld4a(img2 + ii + HW_, c1); ld4a(img2 + ii + 2 * HW_, c2);
#pragma unroll
        for (int i = 0; i < 4; i++) {
            po[2 * i]     = __floats2half2_rn(c0[i], c1[i]);
            po[2 * i + 1] = __floats2half2_rn(c2[i], 0.0f);
        }
        *reinterpret_cast<uint4*>(g_imgp2 + (size_t)px * 4)     = *reinterpret_cast<uint4*>(po);
        *reinterpret_cast<uint4*>(g_imgp2 + (size_t)px * 4 + 8) = *reinterpret_cast<uint4*>(po + 4);
    }

    cudaTriggerProgrammaticLaunchCompletion();

    blockReduceAdd(&g_acc[1], ent);
    blockReduceAdd(&g_acc[2], epe);
}

// Pass 2: grid = (H, B, 2). One row per block; 2 px per thread. PDL consumer.
__global__ void dir_kernel() {
    int dirn = blockIdx.z;
    const __half* __restrict__ fla = dirn ? g_flowhb : g_flowhf;
    const __half* __restrict__ flb = dirn ? g_flowhf : g_flowhb;
    const __half* __restrict__ ipa = dirn ? g_imgp2 : g_imgp1;
    const __half* __restrict__ ipb = dirn ? g_imgp1 : g_imgp2;

    int b = blockIdx.y;
    int y = blockIdx.x;
    int x = threadIdx.x * 2;
    int r = y * W_ + x;

    const __half* fap = fla + (size_t)(b * HW_) * 2;
    const __half* fbp = flb + (size_t)(b * HW_) * 2;
    const __half* iap = ipa + (size_t)(b * HW_) * 4;
    const __half* ibp = ipb + (size_t)(b * HW_) * 4;

    cudaGridDependencySynchronize();

    float f[4];
    ldh4(fap + (size_t)r * 2, f);
    bool hasR1 = (threadIdx.x < (W_ / 2 - 1));
    float2 fr = make_float2(0.0f, 0.0f);
    if (hasR1) fr = ldh2(fap + (size_t)(r + 2) * 2);
    bool hasD = (y < H_ - 1);
    float fd[4];
    if (hasD) ldh4(fap + (size_t)(r + W_) * 2, fd); else zero4(fd);

    float av[8];
    ld8h(iap + (size_t)r * 4, av);

    float e = 0.0f;
    __half mh[2];
    __half2 dh[3];

#pragma unroll
    for (int j = 0; j < 2; j++) {
        float fa0 = f[2 * j], fa1 = f[2 * j + 1];
        float xq = (float)(x + j) + fa0;
        float yq = (float)y + fa1;

        float mx = sigm(xq + 0.5f) * (1.0f - sigm(xq - ((float)W_ - 0.5f)));
        float my = sigm(yq + 0.5f) * (1.0f - sigm(yq - ((float)H_ - 0.5f)));
        float bmask = mx * my;

        float x0f = floorf(xq), y0f = floorf(yq);
        float wx = xq - x0f, wy = yq - y0f;
        int x0 = (int)x0f, y0 = (int)y0f;
        int x1 = x0 + 1,   y1 = y0 + 1;
        float vx0 = (x0 >= 0 && x0 <= W_ - 1) ? 1.0f : 0.0f;
        float vx1 = (x1 >= 0 && x1 <= W_ - 1) ? 1.0f : 0.0f;
        float vy0 = (y0 >= 0 && y0 <= H_ - 1) ? 1.0f : 0.0f;
        float vy1 = (y1 >= 0 && y1 <= H_ - 1) ? 1.0f : 0.0f;
        float w00 = (1.0f - wx) * (1.0f - wy) * vx0 * vy0;
        float w10 = wx * (1.0f - wy) * vx1 * vy0;
        float w01 = (1.0f - wx) * wy * vx0 * vy1;
        float w11 = wx * wy * vx1 * vy1;
        int xc0 = min(max(x0, 0), W_ - 1), xc1 = min(max(x1, 0), W_ - 1);
        int yc0 = min(max(y0, 0), H_ - 1), yc1 = min(max(y1, 0), H_ - 1);
        int o00 = yc0 * W_ + xc0, o10 = yc0 * W_ + xc1;
        int o01 = yc1 * W_ + xc0, o11 = yc1 * W_ + xc1;

        float2 g00 = ldh2(fbp + (size_t)o00 * 2);
        float2 g10 = ldh2(fbp + (size_t)o10 * 2);
        float2 g01 = ldh2(fbp + (size_t)o01 * 2);
        float2 g11 = ldh2(fbp + (size_t)o11 * 2);
        float fw0 = w00 * g00.x + w10 * g10.x + w01 * g01.x + w11 * g11.x;
        float fw1 = w00 * g00.y + w10 * g10.y + w01 * g01.y + w11 * g11.y;

        float mag = fa0 * fa0 + fa1 * fa1 + fw0 * fw0 + fw1 * fw1;
        float d0 = fa0 + fw0, d1 = fa1 + fw1;
        float D = d0 * d0 + d1 * d1;
        float occ = 1.0f - sigm(D - (0.01f * mag + 0.5f));
        float m = bmask * occ;
        mh[j] = __float2half(m);

        float t00[4], t10[4], t01[4], t11[4];
        ldh4(ibp + (size_t)o00 * 4, t00);
        ldh4(ibp + (size_t)o10 * 4, t10);
        ldh4(ibp + (size_t)o01 * 4, t01);
        ldh4(ibp + (size_t)o11 * 4, t11);

        float A = 0.0f;
#pragma unroll
        for (int c = 0; c < 3; c++) {
            float v = w00 * t00[c] + w10 * t10[c] + w01 * t01[c] + w11 * t11[c];
            float dd = av[4 * j + c] - v;
            if (j == 0) dh[c].x = __float2half(dd);
            else        dh[c].y = __float2half(dd);
            A += dd * dd;
        }

        e += (1.0f - m)
           + fsqrtp(A + 1e-5f) * m
           + fsqrtp(D + 1e-5f) * m;

        float s = 0.0f;
        if (j == 0) {
            float a0 = f[2] - fa0, a1 = f[3] - fa1;
            s += a0 * a0 + a1 * a1;
        } else if (hasR1) {
            float a0 = fr.x - fa0, a1 = fr.y - fa1;
            s += a0 * a0 + a1 * a1;
        }
        if (hasD) {
            float a0 = fd[2 * j] - fa0, a1 = fd[2 * j + 1] - fa1;
            s += a0 * a0 + a1 * a1;
        }
        e += fsqrtp(s + 1e-5f);
    }

    size_t pp = (size_t)dirn * NPIX + (size_t)b * HW_ + r;
    *reinterpret_cast<__half2*>(g_maskh + pp) = *reinterpret_cast<__half2*>(mh);
    __half* dw = g_diffh + ((size_t)dirn * B_ + b) * 3 * HW_ + r;
#pragma unroll
    for (int c = 0; c < 3; c++)
        *reinterpret_cast<__half2*>(dw + c * HW_) = dh[c];

    cudaTriggerProgrammaticLaunchCompletion();

    blockReduceAdd(&g_acc[0], e);
}

// Pass 3: grid = (H/4, B, 2). 5-tap gradient on fp16 diff via smem tile.
__global__ void __launch_bounds__(256) grad_kernel(float* __restrict__ out) {
    __shared__ __half sd[3][8][GROWW];   // 25,344 B

    int dirn = blockIdx.z;
    int b = blockIdx.y;
    int y0 = blockIdx.x * 4;
    int tid = threadIdx.x;

    const __half* dp = g_diffh + ((size_t)dirn * B_ + b) * 3 * HW_;

    // zero the left/right aprons: 3ch x 8rows x 2 sides, 8 halves (16B) each
    if (tid < 48) {
        int c = tid / 16;
        int k = (tid & 15) >> 1;
        int side = tid & 1;
        uint4 z = make_uint4(0, 0, 0, 0);
        *reinterpret_cast<uint4*>(&sd[c][k][side ? (GPAD + W_) : 0]) = z;
    }

    cudaGridDependencySynchronize();

    // cooperative load: 3ch x 8 rows x 64 chunks of 8 halves = 1536 chunks
#pragma unroll
    for (int i = 0; i < 6; i++) {
        int id = tid + i * 256;
        int c   = id >> 9;
        int rem = id & 511;
        int k   = rem >> 6;
        int xc  = rem & 63;
        int yy  = y0 - 2 + k;
        uint4 v = make_uint4(0, 0, 0, 0);
        if (yy >= 0 && yy < H_)
            v = *reinterpret_cast<const uint4*>(dp + c * HW_ + yy * W_ + xc * 8);
        *reinterpret_cast<uint4*>(&sd[c][k][GPAD + xc * 8]) = v;
    }
    __syncthreads();

    int sub = tid >> 6;
    int x = (tid & 63) * 8;
    int kc = sub + 2;
    int y = y0 + sub;

    float Ct[8];
    zero8(Ct);
#pragma unroll
    for (int c = 0; c < 3; c++) {
        float arr[12];
        ld8h(&sd[c][kc][GPAD + x], arr + 2);
        float2 lf = ldh2(&sd[c][kc][GPAD + x - 2]);
        float2 rf = ldh2(&sd[c][kc][GPAD + x + 8]);
        arr[0] = lf.x; arr[1] = lf.y;
        arr[10] = rf.x; arr[11] = rf.y;

        float u2[8], u1[8], dn1[8], dn2[8];
        ld8h(&sd[c][kc - 2][GPAD + x], u2);
        ld8h(&sd[c][kc - 1][GPAD + x], u1);
        ld8h(&sd[c][kc + 1][GPAD + x], dn1);
        ld8h(&sd[c][kc + 2][GPAD + x], dn2);

#pragma unroll
        for (int j = 0; j < 8; j++) {
            float gx = K0 * arr[j] + K1 * arr[j + 1] + K3 * arr[j + 3] + K4 * arr[j + 4];
            float gy = K0 * u2[j] + K1 * u1[j] + K3 * dn1[j] + K4 * dn2[j];
            Ct[j] += gx * gx + gy * gy;
        }
    }

    float m[8];
    ld8h(g_maskh + (size_t)dirn * NPIX + (size_t)b * HW_ + (size_t)y * W_ + x, m);
    float e = 0.0f;
#pragma unroll
    for (int j = 0; j < 8; j++) e += fsqrtp(Ct[j] + 1e-5f) * m[j];

    blockReduceAdd(&g_acc[0], e);

    // ---- fused finalize ----
    if (threadIdx.x == 0) {
        __threadfence();
        unsigned total = gridDim.x * gridDim.y * gridDim.z;
        if (atomicAdd(&g_done, 1u) == total - 1u) {
            double energy  = g_acc[0];
            double entropy = 0.5 * g_acc[1];
            out[0] = (float)((energy - entropy) / (double)B_);
            out[1] = (float)(g_acc[2] / (double)NPIX);
            g_acc[0] = 0.0; g_acc[1] = 0.0; g_acc[2] = 0.0;
            g_done = 0;
        }
    }
}

extern "C" void kernel_launch(void* const* d_in, const int* in_sizes, int n_in,
                              void* d_out, int out_size) {
    const float* meanf   = (const float*)d_in[0];
    const float* logvarf = (const float*)d_in[1];
    const float* meanb   = (const float*)d_in[2];
    const float* logvarb = (const float*)d_in[3];
    const float* img1    = (const float*)d_in[4];
    const float* img2    = (const float*)d_in[5];
    const float* target  = (const float*)d_in[6];
    const float* noisef  = (const float*)d_in[7];
    const float* noiseb  = (const float*)d_in[8];
    float* out = (float*)d_out;

    {
        dim3 g(HW_ / 4 / 256, B_);
        sample_kernel<<<g, 256>>>(meanf, logvarf, noisef,
                                  meanb, logvarb, noiseb, target,
                                  img1, img2);
    }

    cudaLaunchAttribute attr[1];
    attr[0].id = cudaLaunchAttributeProgrammaticStreamSerialization;
    attr[0].val.programmaticStreamSerializationAllowed = 1;

    {
        cudaLaunchConfig_t cfg = {};
        cfg.gridDim = dim3(H_, B_, 2);
        cfg.blockDim = dim3(256);
        cfg.attrs = attr;
        cfg.numAttrs = 1;
        cudaLaunchKernelEx(&cfg, dir_kernel);
    }
    {
        cudaLaunchConfig_t cfg = {};
        cfg.gridDim = dim3(H_ / 4, B_, 2);
        cfg.blockDim = dim3(256);
        cfg.attrs = attr;
        cfg.numAttrs = 1;
        cudaLaunchKernelEx(&cfg, grad_kernel, out);
    }
}